// round 7
// baseline (speedup 1.0000x reference)
#include <cuda_runtime.h>

#define H 512
#define LSEQ 1024
#define NROWS 4096
#define NST 64

typedef unsigned long long u64;

// ---- packed f32x2 (FFMA2) helpers ----
__device__ __forceinline__ u64 pack2(float x, float y) {
    u64 r; asm("mov.b64 %0,{%1,%2};" : "=l"(r) : "f"(x), "f"(y)); return r;
}
__device__ __forceinline__ u64 dup2(float x) { return pack2(x, x); }
__device__ __forceinline__ void unpack2(u64 v, float& x, float& y) {
    asm("mov.b64 {%0,%1},%2;" : "=f"(x), "=f"(y) : "l"(v));
}
__device__ __forceinline__ void fma2(u64& d, u64 a, u64 b) {
    asm("fma.rn.f32x2 %0,%1,%2,%0;" : "+l"(d) : "l"(a), "l"(b));
}

// ---- complex helpers ----
__device__ __forceinline__ float2 cmul(float2 a, float2 b) {
    return make_float2(a.x*b.x - a.y*b.y, a.x*b.y + a.y*b.x);
}
__device__ __forceinline__ float2 cadd(float2 a, float2 b) { return make_float2(a.x+b.x, a.y+b.y); }
__device__ __forceinline__ float2 csub(float2 a, float2 b) { return make_float2(a.x-b.x, a.y-b.y); }
__device__ __forceinline__ float2 cscale(float2 a, float s) { return make_float2(a.x*s, a.y*s); }
__device__ __forceinline__ float2 cinv(float2 d) {
    float inv = 1.f / (d.x*d.x + d.y*d.y);
    return make_float2(d.x*inv, -d.y*inv);
}

// ---- scratch: device globals (sanctioned; no runtime allocation) ----
__device__ float  g_xn[NROWS * H];
__device__ float  g_yg[NROWS * H];
__device__ float  g_part[8][NROWS * H];
__device__ float2 g_M[2][NST * NST];
__device__ float2 g_S[NST * NST];
__device__ float  g_K[LSEQ];

// ================= LayerNorm =================
__global__ void k_ln(const float* __restrict__ x, const float* __restrict__ w,
                     const float* __restrict__ bi) {
    int row = blockIdx.x;
    int t = threadIdx.x;  // 128 threads, float4 each
    float4 v = ((const float4*)(x + (size_t)row * H))[t];
    float s  = v.x + v.y + v.z + v.w;
    float ss = v.x*v.x + v.y*v.y + v.z*v.z + v.w*v.w;
    __shared__ float rs[4], rss[4];
#pragma unroll
    for (int o = 16; o > 0; o >>= 1) {
        s  += __shfl_down_sync(0xffffffffu, s, o);
        ss += __shfl_down_sync(0xffffffffu, ss, o);
    }
    if ((t & 31) == 0) { rs[t >> 5] = s; rss[t >> 5] = ss; }
    __syncthreads();
    float sum = rs[0] + rs[1] + rs[2] + rs[3];
    float sq  = rss[0] + rss[1] + rss[2] + rss[3];
    float mu = sum * (1.f / H);
    float var = sq * (1.f / H) - mu * mu;
    float rstd = rsqrtf(var + 1e-5f);
    float4 wv = ((const float4*)w)[t];
    float4 bv = ((const float4*)bi)[t];
    float4 o;
    o.x = (v.x - mu) * rstd * wv.x + bv.x;
    o.y = (v.y - mu) * rstd * wv.y + bv.y;
    o.z = (v.z - mu) * rstd * wv.z + bv.z;
    o.w = (v.w - mu) * rstd * wv.w + bv.w;
    ((float4*)(g_xn + (size_t)row * H))[t] = o;
}

// ================= S4 setup (64 threads) =================
__device__ __forceinline__ float2 reduce64(float2 val, float2* red) {
    int i = threadIdx.x;
#pragma unroll
    for (int o = 16; o > 0; o >>= 1) {
        val.x += __shfl_down_sync(0xffffffffu, val.x, o);
        val.y += __shfl_down_sync(0xffffffffu, val.y, o);
    }
    if ((i & 31) == 0) red[i >> 5] = val;
    __syncthreads();
    float2 r = cadd(red[0], red[1]);
    __syncthreads();
    return r;
}

__global__ void k_setup(const float* lre, const float* lim, const float* pre, const float* pim,
                        const float* bre, const float* bim, const float* logstep) {
    int i = threadIdx.x;  // 64 threads
    __shared__ float2 sh_v[NST];
    __shared__ float2 red[2];
    float dt = expf(logstep[0]);
    float w0 = 2.f / dt;
    float2 lam = make_float2(lre[i], lim[i]);
    float2 p   = make_float2(pre[i], pim[i]);
    float2 bb  = make_float2(bre[i], bim[i]);
    float2 D  = cinv(make_float2(w0 - lam.x, -lam.y));
    float2 d0 = make_float2(w0 + lam.x, lam.y);
    float pn2 = p.x*p.x + p.y*p.y;
    float2 sig = reduce64(cscale(D, pn2), red);
    float2 alpha = cinv(make_float2(1.f + sig.x, sig.y));
    float2 u = cmul(D, p);
    float2 g = cmul(D, d0);
    float2 as = cmul(alpha, sig);
    float2 coef = csub(make_float2(as.x - 1.f, as.y), cmul(alpha, g));
    float2 v = cmul(make_float2(p.x, -p.y), coef);
    float2 Db = cmul(D, bb);
    float2 tau = reduce64(cmul(make_float2(p.x, -p.y), Db), red);
    float2 Bv = cscale(csub(Db, cmul(cmul(alpha, tau), u)), 2.f);
    sh_v[i] = v;
    __syncthreads();
    // Ab[i][j] = u_i * v_j + delta_ij * g_i
    for (int j = 0; j < NST; j++) {
        float2 e = cmul(u, sh_v[j]);
        if (j == i) e = cadd(e, g);
        g_M[0][i * NST + j] = e;
    }
    // s_k chain: s_{k+1} = g .* s + u * (v . s)
    float2 s = Bv;
    g_S[0 * NST + i] = s;
    for (int k = 1; k < NST; k++) {
        float2 dot = reduce64(cmul(v, s), red);
        s = cadd(cmul(g, s), cmul(u, dot));
        g_S[k * NST + i] = s;
    }
}

// ================= 64x64 complex squaring =================
__global__ void k_sq(int srcsel) {
    const float2* Min = g_M[srcsel];
    float2* Mout = g_M[srcsel ^ 1];
    __shared__ float2 rowi[NST];
    int i = blockIdx.x, j = threadIdx.x;
    rowi[j] = Min[i * NST + j];
    __syncthreads();
    float2 acc = make_float2(0.f, 0.f);
#pragma unroll
    for (int n = 0; n < NST; n++) acc = cadd(acc, cmul(rowi[n], Min[n * NST + j]));
    Mout[i * NST + j] = acc;
}

// ================= K[64m+k] = Re(r_m . s_k) =================
__global__ void k_kfinal(const float* cre, const float* cim) {
    int i = threadIdx.x;  // 64
    __shared__ float2 r[NST], rn[NST];
    r[i] = make_float2(cre[i], cim[i]);
    __syncthreads();
    const float2* M = g_M[0];  // Ab^64 after 6 squarings
    for (int m = 0; m < 16; m++) {
        float2 acc = make_float2(0.f, 0.f);  // K[64m + i] = sum_n r[n]*S[i][n]
#pragma unroll
        for (int n = 0; n < NST; n++) acc = cadd(acc, cmul(r[n], g_S[i * NST + n]));
        g_K[m * NST + i] = acc.x;
        float2 a2 = make_float2(0.f, 0.f);   // r <- M^T r
#pragma unroll
        for (int n = 0; n < NST; n++) a2 = cadd(a2, cmul(r[n], M[n * NST + i]));
        rn[i] = a2;
        __syncthreads();
        r[i] = rn[i];
        __syncthreads();
    }
}

// ================= causal Toeplitz conv, split-buffer partials =================
// grid 576 = 4 b x 4 hT x 36 triangular (tT,sT); 128x128x128 tile per block
__global__ void __launch_bounds__(256, 2) k_conv() {
    int idx = blockIdx.x;
    int b = idx / 144;
    int rem = idx - b * 144;
    int hT = rem / 36;
    int pr = rem - hT * 36;
    int tT = 0;
    while ((tT + 1) * (tT + 2) / 2 <= pr) tT++;
    int sT = pr - tT * (tT + 1) / 2;
    int t0 = tT * 128, s0 = sT * 128, h0 = hT * 128;
    int D0 = t0 - s0;

    __shared__ float Ks[264];
    __shared__ float Xs[32][128];
    const float* X = g_xn + (size_t)(b * LSEQ) * H;
    int tid = threadIdx.x;
    for (int jj = tid; jj < 264; jj += 256) {
        int d = D0 + jj - 131;
        Ks[jj] = (d >= 0 && d < LSEQ) ? g_K[d] : 0.f;
    }
    int ty = tid >> 4, tx = tid & 15;  // ty: 8 t-rows each; tx: 8 h-cols (tx*2 + 32j)
    u64 acc[8][4];
#pragma unroll
    for (int r = 0; r < 8; r++)
#pragma unroll
        for (int c = 0; c < 4; c++) acc[r][c] = 0ull;

    const float* KSp = Ks + 131 + ty * 8;  // KSp[x] = K[D0 + ty*8 + x]

    for (int ch = 0; ch < 4; ch++) {
        __syncthreads();
        {   // load 32 x 128 chunk of X (coalesced float4)
            int rr = tid >> 5;
            int cc = (tid & 31) * 4;
            const float* src = X + (size_t)(s0 + ch * 32 + rr) * H + h0 + cc;
#pragma unroll
            for (int k2 = 0; k2 < 4; k2++)
                *(float4*)&Xs[rr + k2 * 8][cc] = *(const float4*)(src + (size_t)(k2 * 8) * H);
        }
        __syncthreads();
        int base = -ch * 32;
        u64 a2[8];
#pragma unroll
        for (int r = 0; r < 8; r++) a2[r] = dup2(KSp[base + r]);
#pragma unroll
        for (int sl = 0; sl < 32; sl++) {
            u64 xv[4];
#pragma unroll
            for (int c = 0; c < 4; c++) xv[c] = *(const u64*)&Xs[sl][tx * 2 + c * 32];
#pragma unroll
            for (int r = 0; r < 8; r++)
#pragma unroll
                for (int c = 0; c < 4; c++) fma2(acc[r][c], a2[r], xv[c]);
#pragma unroll
            for (int r = 7; r > 0; r--) a2[r] = a2[r - 1];
            a2[0] = dup2(KSp[base - sl - 1]);
        }
    }
    float* P = g_part[sT] + ((size_t)(b * LSEQ) + t0) * H + h0;
#pragma unroll
    for (int r = 0; r < 8; r++) {
        float* Pr = P + (size_t)(ty * 8 + r) * H + tx * 2;
#pragma unroll
        for (int c = 0; c < 4; c++) {
            float va, vb; unpack2(acc[r][c], va, vb);
            *(float2*)(Pr + c * 32) = make_float2(va, vb);
        }
    }
}

// ================= split reduce + d*xn + GELU =================
__global__ void k_gelu(const float* __restrict__ dscale) {
    int idx = blockIdx.x * 256 + threadIdx.x;
    int row = idx >> 7, c4 = idx & 127;
    int t = row & (LSEQ - 1);
    int tT = t >> 7;
    size_t off = (size_t)row * H + c4 * 4;
    float4 s = make_float4(0.f, 0.f, 0.f, 0.f);
    for (int j = 0; j <= tT; j++) {
        float4 p = *(const float4*)(g_part[j] + off);
        s.x += p.x; s.y += p.y; s.z += p.z; s.w += p.w;
    }
    float dv = dscale[0];
    float4 xn = *(const float4*)(g_xn + off);
    float y0 = s.x + dv * xn.x, y1 = s.y + dv * xn.y;
    float y2 = s.z + dv * xn.z, y3 = s.w + dv * xn.w;
    // gelu(y) = y / (1 + exp(-2z)), z = 0.79788456*(y + 0.044715 y^3)
    float4 o;
    float z;
    z = 0.7978845608f * (y0 + 0.044715f * y0 * y0 * y0); o.x = y0 / (1.f + __expf(-2.f * z));
    z = 0.7978845608f * (y1 + 0.044715f * y1 * y1 * y1); o.y = y1 / (1.f + __expf(-2.f * z));
    z = 0.7978845608f * (y2 + 0.044715f * y2 * y2 * y2); o.z = y2 / (1.f + __expf(-2.f * z));
    z = 0.7978845608f * (y3 + 0.044715f * y3 * y3 * y3); o.w = y3 / (1.f + __expf(-2.f * z));
    *(float4*)(g_yg + off) = o;
}

// ================= fused dual GEMM + sigmoid gate + residual =================
// grid (32, 8): 128 rows x 64 out-cols of BOTH matrices per block
__global__ void __launch_bounds__(256, 2) k_gemm(
    const float* __restrict__ W1, const float* __restrict__ W2,
    const float* __restrict__ b1, const float* __restrict__ b2,
    const float* __restrict__ skip, float* __restrict__ out) {
    __shared__ float As[32][132];
    __shared__ float Bs[32][132];
    int r0 = blockIdx.x * 128, o0 = blockIdx.y * 64;
    int tid = threadIdx.x, ty = tid >> 4, tx = tid & 15;
    int rr = tid & 127, half = tid >> 7;
    u64 acc[8][4];
#pragma unroll
    for (int r = 0; r < 8; r++)
#pragma unroll
        for (int j = 0; j < 4; j++) acc[r][j] = 0ull;
    // B loader: smem cols 0..63 <- W1[o0..o0+63], 64..127 <- W2[o0..o0+63]
    const float* Bsrc = (rr < 64) ? (W1 + (size_t)(o0 + rr) * H)
                                  : (W2 + (size_t)(o0 + rr - 64) * H);
    const float* Asrc = g_yg + (size_t)(r0 + rr) * H;

    for (int kc = 0; kc < 16; kc++) {
        __syncthreads();
        int kb = kc * 32 + half * 16;
#pragma unroll
        for (int q = 0; q < 4; q++) {
            float4 av = *(const float4*)(Asrc + kb + q * 4);
            int kk = half * 16 + q * 4;
            As[kk + 0][rr] = av.x; As[kk + 1][rr] = av.y;
            As[kk + 2][rr] = av.z; As[kk + 3][rr] = av.w;
            float4 bv = *(const float4*)(Bsrc + kb + q * 4);
            Bs[kk + 0][rr] = bv.x; Bs[kk + 1][rr] = bv.y;
            Bs[kk + 2][rr] = bv.z; Bs[kk + 3][rr] = bv.w;
        }
        __syncthreads();
#pragma unroll
        for (int kk = 0; kk < 32; kk++) {
            float4 a0 = *(const float4*)&As[kk][ty * 8];
            float4 a1 = *(const float4*)&As[kk][ty * 8 + 4];
            u64 bb[4];
#pragma unroll
            for (int j = 0; j < 4; j++) bb[j] = *(const u64*)&Bs[kk][tx * 2 + j * 32];
            u64 ad[8] = { dup2(a0.x), dup2(a0.y), dup2(a0.z), dup2(a0.w),
                          dup2(a1.x), dup2(a1.y), dup2(a1.z), dup2(a1.w) };
#pragma unroll
            for (int r = 0; r < 8; r++)
#pragma unroll
                for (int j = 0; j < 4; j++) fma2(acc[r][j], ad[r], bb[j]);
        }
    }
    // epilogue: j=0,1 hold P1 (proj), j=2,3 hold P2 (gate) at same out-cols
#pragma unroll
    for (int r = 0; r < 8; r++) {
        int row = r0 + ty * 8 + r;
        const float* sk = skip + (size_t)row * H;
        float* op = out + (size_t)row * H;
#pragma unroll
        for (int j = 0; j < 2; j++) {
            int o = o0 + tx * 2 + j * 32;
            float p1a, p1b, p2a, p2b;
            unpack2(acc[r][j], p1a, p1b);
            unpack2(acc[r][j + 2], p2a, p2b);
            float v1 = p1a + b1[o], v2 = p1b + b1[o + 1];
            float g1 = p2a + b2[o], g2 = p2b + b2[o + 1];
            float o1 = sk[o]     + v1 / (1.f + __expf(-g1));
            float o2 = sk[o + 1] + v2 / (1.f + __expf(-g2));
            *(float2*)(op + o) = make_float2(o1, o2);
        }
    }
}

extern "C" void kernel_launch(void* const* d_in, const int* in_sizes, int n_in,
                              void* d_out, int out_size) {
    const float* x   = (const float*)d_in[0];
    const float* nw  = (const float*)d_in[1];
    const float* nb  = (const float*)d_in[2];
    const float* lre = (const float*)d_in[3];
    const float* lim = (const float*)d_in[4];
    const float* pre = (const float*)d_in[5];
    const float* pim = (const float*)d_in[6];
    const float* bre = (const float*)d_in[7];
    const float* bim = (const float*)d_in[8];
    const float* cre = (const float*)d_in[9];
    const float* cim = (const float*)d_in[10];
    const float* dd  = (const float*)d_in[11];
    const float* ls  = (const float*)d_in[12];
    const float* W1  = (const float*)d_in[13];
    const float* b1  = (const float*)d_in[14];
    const float* W2  = (const float*)d_in[15];
    const float* b2  = (const float*)d_in[16];
    float* out = (float*)d_out;

    k_ln<<<NROWS, 128>>>(x, nw, nb);
    k_setup<<<1, 64>>>(lre, lim, pre, pim, bre, bim, ls);
    for (int i = 0; i < 6; i++) k_sq<<<NST, NST>>>(i & 1);
    k_kfinal<<<1, 64>>>(cre, cim);
    k_conv<<<576, 256>>>();
    k_gelu<<<2048, 256>>>(dd);
    k_gemm<<<dim3(32, 8), 256>>>(W1, W2, b1, b2, x, out);
}